// round 17
// baseline (speedup 1.0000x reference)
#include <cuda_runtime.h>
#include <cstdint>
#include <float.h>

#define BB 16
#define NN 2048
#define CC 80
#define NBK 2048          // key buckets (mantissa bits [22:12])

// ---------------- scratch (device globals; no allocations) ----------------
__device__ float4             g_xyxy [BB * NN];
__device__ float              g_obj  [BB * NN];
__device__ float              g_conf [BB * NN];
__device__ int                g_cls  [BB * NN];
__device__ unsigned long long g_key64[BB * NN];

// ---------------- kernel 1: prep, 8 threads/element, valid-gated ----------
__global__ __launch_bounds__(128) void prep_kernel(const float* __restrict__ boxes,
                                                   const float* __restrict__ objn,
                                                   const float* __restrict__ logits,
                                                   float* __restrict__ out)
{
    int gid = blockIdx.x * blockDim.x + threadIdx.x;
    int gw  = gid >> 3;             // element index
    int sub = gid & 7;              // 0..7 within element group
    if (gw >= BB * NN) return;

    float ob = objn[gw];            // broadcast-coalesced within group
    bool valid = ob > 0.5f;

    if (sub == 0) {
        unsigned u = __float_as_uint(valid ? ob : -1.0f);
        u = (u & 0x80000000u) ? ~u : (u | 0x80000000u);
        unsigned idx = (unsigned)(gw & (NN - 1));
        g_key64[gw] = ((unsigned long long)u << 32) | (0xFFFFFFFFu - idx);
        int b = gw >> 11;
        ((float4*)(out + (size_t)gw * 8))[0] = make_float4((float)b, 0.f, 0.f, 0.f);
    } else if (sub == 1) {
        ((float4*)(out + (size_t)gw * 8))[1] = make_float4(0.f, 0.f, 0.f, 0.f);
    }

    if (!valid) return;             // whole 8-lane group shares gw -> uniform exit

    // subs 0-3: 3 float4 (classes sub*12..+11); subs 4-7: 2 float4 (48+(sub-4)*8..+7)
    const float4* base4 = (const float4*)(logits + (size_t)gw * CC);
    float v = -FLT_MAX;
    int   vi = 0;
    if (sub < 4) {
        const float4* lg4 = base4 + sub * 3;
        int k0 = sub * 12;
        #pragma unroll
        for (int q = 0; q < 3; q++) {
            float4 x = lg4[q];
            int k = k0 + q * 4;
            if (x.x > v) { v = x.x; vi = k;     }
            if (x.y > v) { v = x.y; vi = k + 1; }
            if (x.z > v) { v = x.z; vi = k + 2; }
            if (x.w > v) { v = x.w; vi = k + 3; }
        }
    } else {
        const float4* lg4 = base4 + 12 + (sub - 4) * 2;
        int k0 = 48 + (sub - 4) * 8;
        #pragma unroll
        for (int q = 0; q < 2; q++) {
            float4 x = lg4[q];
            int k = k0 + q * 4;
            if (x.x > v) { v = x.x; vi = k;     }
            if (x.y > v) { v = x.y; vi = k + 1; }
            if (x.z > v) { v = x.z; vi = k + 2; }
            if (x.w > v) { v = x.w; vi = k + 3; }
        }
    }
    // reduce across the 8-lane group (explicit group mask), tie -> lowest index
    unsigned gmask = 0xFFu << ((threadIdx.x & 31) & ~7);
    #pragma unroll
    for (int o = 1; o <= 4; o <<= 1) {
        float v2 = __shfl_xor_sync(gmask, v, o);
        int   i2 = __shfl_xor_sync(gmask, vi, o);
        if (v2 > v || (v2 == v && i2 < vi)) { v = v2; vi = i2; }
    }

    if (sub == 0) {
        float4 bx = ((const float4*)boxes)[gw];
        float4 xy;
        xy.x = bx.x - bx.z * 0.5f;
        xy.y = bx.y - bx.w * 0.5f;
        xy.z = bx.x + bx.z * 0.5f;
        xy.w = bx.y + bx.w * 0.5f;
        g_xyxy[gw] = xy;
        g_obj [gw] = ob;
        g_conf[gw] = v;
        g_cls [gw] = vi;
    }
}

// ---------------- kernel 2: NMS with per-block redundant counting sort ----
// 160 blocks = (batch, 8-class group); each block redoes its batch's counting
// sort entirely in smem (keys L2-hot), then 8 warps run per-class NMS.
#define NMS_CW 8                 // classes (=warps) per block
#define NMS_GRP (CC / NMS_CW)    // 10 groups per batch
#define NMS_THREADS 256
#define EPT 8                    // elements per thread (2048/256)
#define LCAP 128

struct NSmem {
    int                hist[NBK];            // counts, then scatter cursors
    int                offs[NBK];            // bucket start offsets (desc order)
    unsigned long long skey[NN];             // sorted keys
    float4             sbox[NN];             // sorted xyxy
    unsigned char      scls[NN];             // sorted class
    unsigned short     sidx[NN];             // sorted pos -> original idx
    unsigned short     list [NMS_CW][LCAP];
    unsigned char      alive[NMS_CW][LCAP];
    int                wsum[NMS_CW];
    int                Msh;
};

__global__ __launch_bounds__(NMS_THREADS) void nms_kernel(float* __restrict__ out)
{
    extern __shared__ char raw[];
    NSmem* sm = (NSmem*)raw;

    int t    = threadIdx.x;
    int warp = t >> 5;
    int lane = t & 31;
    int b    = blockIdx.x / NMS_GRP;
    int grp  = blockIdx.x % NMS_GRP;

    // ---- zero histogram ----
    #pragma unroll
    for (int r = 0; r < NBK / NMS_THREADS; r++) sm->hist[t + r * NMS_THREADS] = 0;
    __syncthreads();

    // ---- load keys (8/thread, coalesced) + histogram ----
    unsigned long long key[EPT];
    int  kb[EPT];
    bool kv[EPT];
    #pragma unroll
    for (int r = 0; r < EPT; r++) {
        key[r] = g_key64[b * NN + t + r * NMS_THREADS];
        kv[r]  = (unsigned)(key[r] >> 32) > 0x80000000u;
        kb[r]  = (int)((key[r] >> 44) & (NBK - 1));
        if (kv[r]) atomicAdd(&sm->hist[kb[r]], 1);
    }
    __syncthreads();

    // ---- descending exclusive scan (8 buckets per thread) ----
    int cnt[EPT];
    int sum = 0;
    #pragma unroll
    for (int i = 0; i < EPT; i++) {
        cnt[i] = sm->hist[NBK - 1 - (EPT * t + i)];
        sum += cnt[i];
    }
    int inc = sum;
    #pragma unroll
    for (int o = 1; o < 32; o <<= 1) {
        int a = __shfl_up_sync(0xFFFFFFFFu, inc, o);
        if (lane >= o) inc += a;
    }
    if (lane == 31) sm->wsum[warp] = inc;
    __syncthreads();
    if (warp == 0 && lane < NMS_CW) {
        int wv = sm->wsum[lane];
        int winc = wv;
        #pragma unroll
        for (int o = 1; o < NMS_CW; o <<= 1) {
            int a = __shfl_up_sync(0x000000FFu, winc, o);
            if (lane >= o) winc += a;
        }
        sm->wsum[lane] = winc - wv;      // exclusive warp offsets
    }
    __syncthreads();
    int run = sm->wsum[warp] + (inc - sum);
    #pragma unroll
    for (int i = 0; i < EPT; i++) {
        sm->offs[NBK - 1 - (EPT * t + i)] = run;
        run += cnt[i];
    }
    if (t == NMS_THREADS - 1) sm->Msh = run;    // covers desc tail -> total
    __syncthreads();

    // ---- cursors = offs; scatter keys into bucket slots ----
    #pragma unroll
    for (int r = 0; r < NBK / NMS_THREADS; r++)
        sm->hist[t + r * NMS_THREADS] = sm->offs[t + r * NMS_THREADS];
    __syncthreads();
    #pragma unroll
    for (int r = 0; r < EPT; r++) {
        if (kv[r]) {
            int s = atomicAdd(&sm->hist[kb[r]], 1);
            sm->skey[s] = key[r];
        }
    }
    __syncthreads();

    // ---- per-bucket insertion sort, descending (stable via idx low bits) --
    #pragma unroll
    for (int i = 0; i < EPT; i++) {
        int bk = EPT * t + i;
        int s = sm->offs[bk], e = sm->hist[bk];
        for (int p = s + 1; p < e; p++) {
            unsigned long long k2 = sm->skey[p];
            int j = p - 1;
            while (j >= s && sm->skey[j] < k2) { sm->skey[j + 1] = sm->skey[j]; j--; }
            sm->skey[j + 1] = k2;
        }
    }
    __syncthreads();

    int M = sm->Msh;

    // ---- gather stage: boxes/cls through the permutation ----
    for (int p = t; p < M; p += NMS_THREADS) {
        unsigned n = 0xFFFFFFFFu - (unsigned)(sm->skey[p] & 0xFFFFFFFFu);
        int g = b * NN + (int)n;
        sm->sbox[p] = g_xyxy[g];
        sm->scls[p] = (unsigned char)g_cls[g];
        sm->sidx[p] = (unsigned short)n;
    }
    __syncthreads();

    // ---- warp per class: compaction + greedy NMS + output -----------------
    int c = grp * NMS_CW + warp;
    unsigned short* list  = sm->list [warp];
    unsigned char*  alive = sm->alive[warp];

    int K = 0;
    for (int base = 0; base < M; base += 32) {
        int p = base + lane;
        bool match = (p < M) && (sm->scls[p] == (unsigned char)c);
        unsigned mask = __ballot_sync(0xFFFFFFFFu, match);
        if (match) {
            int d = K + __popc(mask & ((1u << lane) - 1u));
            if (d < LCAP) list[d] = (unsigned short)p;
        }
        K += __popc(mask);
    }
    if (K > LCAP) K = LCAP;
    for (int k2 = lane; k2 < K; k2 += 32) alive[k2] = 1;
    __syncwarp();

    for (int i = 0; i < K - 1; i++) {
        if (alive[i]) {
            float4 bi = sm->sbox[list[i]];
            float areaI = (bi.z - bi.x + 1.0f) * (bi.w - bi.y + 1.0f);
            for (int j = i + 1 + lane; j < K; j += 32) {
                if (alive[j]) {
                    float4 bj = sm->sbox[list[j]];
                    float x1 = fmaxf(bi.x, bj.x);
                    float y1 = fmaxf(bi.y, bj.y);
                    float x2 = fminf(bi.z, bj.z);
                    float y2 = fminf(bi.w, bj.w);
                    float iw = fmaxf(x2 - x1 + 1.0f, 0.0f);
                    float ih = fmaxf(y2 - y1 + 1.0f, 0.0f);
                    float inter = iw * ih;
                    float areaJ = (bj.z - bj.x + 1.0f) * (bj.w - bj.y + 1.0f);
                    float iou = inter / (areaI + areaJ - inter);
                    if (iou >= 0.5f) alive[j] = 0;
                }
            }
        }
        __syncwarp();
    }

    for (int k2 = lane; k2 < K; k2 += 32) {
        if (alive[k2]) {
            int p = list[k2];
            int g = b * NN + sm->sidx[p];
            float4 bx = sm->sbox[p];
            float4* row = (float4*)(out + ((size_t)(b * NN + p)) * 8);
            row[0] = make_float4((float)b, bx.x, bx.y, bx.z);
            row[1] = make_float4(bx.w, g_obj[g], g_conf[g], (float)c);
        }
    }
}

// ---------------- launch ---------------------------------------------------
extern "C" void kernel_launch(void* const* d_in, const int* in_sizes, int n_in,
                              void* d_out, int out_size)
{
    const float* boxes  = nullptr;
    const float* objn   = nullptr;
    const float* logits = nullptr;
    for (int i = 0; i < n_in; i++) {
        if      (in_sizes[i] == BB * NN * 4)  boxes  = (const float*)d_in[i];
        else if (in_sizes[i] == BB * NN)      objn   = (const float*)d_in[i];
        else if (in_sizes[i] == BB * NN * CC) logits = (const float*)d_in[i];
    }
    float* out = (float*)d_out;

    prep_kernel<<<(BB * NN * 8 + 127) / 128, 128>>>(boxes, objn, logits, out);

    size_t smem = sizeof(NSmem);
    cudaFuncSetAttribute(nms_kernel, cudaFuncAttributeMaxDynamicSharedMemorySize,
                         (int)smem);
    nms_kernel<<<BB * NMS_GRP, NMS_THREADS, smem>>>(out);
}